// round 5
// baseline (speedup 1.0000x reference)
#include <cuda_runtime.h>

#define N_NODES 50000
#define N_EDGES 500000
#define NUMK 4
#define FDIM 64
#define DDIM 32
#define NBE 64
#define NBND 63
#define GP 68

// Scratch (device globals)
__device__ __align__(128) float g_y[(size_t)N_NODES * 128];
__device__ float g_s[N_NODES];
__device__ float g_c0[N_NODES];                 // in-degree count (float)
__device__ float g_c2[N_NODES];                 // out-degree count (float)
__device__ __align__(128) float g_T[NBE * FDIM];
__device__ int g_pk[5][N_EDGES];                // packed (other<<6)|bucket, SoA

__device__ __forceinline__ void red_add4(float* p, float x, float y, float z, float w) {
    asm volatile("red.global.add.v4.f32 [%0], {%1,%2,%3,%4};"
                 :: "l"(p), "f"(x), "f"(y), "f"(z), "f"(w) : "memory");
}

// Fused prep: zero y/s/counts, build T table.
__global__ __launch_bounds__(256) void k_prep(
    const float* __restrict__ emb, const float* __restrict__ gw)
{
    int i = blockIdx.x * blockDim.x + threadIdx.x;
    int stride = gridDim.x * blockDim.x;
    float4 z = make_float4(0.f, 0.f, 0.f, 0.f);
    float4* y4 = reinterpret_cast<float4*>(g_y);
    for (int j = i; j < N_NODES * 32; j += stride) y4[j] = z;
    for (int j = i; j < N_NODES; j += stride) {
        g_c0[j] = 0.f; g_c2[j] = 0.f; g_s[j] = 0.f;
    }
    for (int j = i; j < NBE * FDIM; j += stride) {
        int b = j >> 6, f = j & 63;
        float acc = 0.f;
#pragma unroll
        for (int d = 0; d < DDIM; d++) acc += emb[b * DDIM + d] * gw[f * DDIM + d];
        g_T[j] = acc;
    }
}

__global__ void k_deg(const int* __restrict__ src, const int* __restrict__ dst) {
    int e = blockIdx.x * blockDim.x + threadIdx.x;
    if (e < N_EDGES) {
        atomicAdd(&g_c0[dst[e]], 1.f);
        atomicAdd(&g_c2[src[e]], 1.f);
    }
}

// One thread per (edge, slot): bucketize distance, store packed result.
// Block = 320 threads = 64 edges x 5 slots (slot uniform per 2 warps).
__global__ __launch_bounds__(320) void k_dist(
    const float* __restrict__ loc, const float* __restrict__ bnd,
    const int* __restrict__ src, const int* __restrict__ dst,
    const int* __restrict__ inter)
{
    __shared__ float sb2[64];
    int t = threadIdx.x;
    if (t < NBND) { float b = bnd[t]; sb2[t] = b * b; }
    __syncthreads();

    int e = blockIdx.x * 64 + (t & 63);
    int slot = t >> 6;
    if (e >= N_EDGES) return;

    int si = __ldg(&src[e]);
    int other = (slot == 0) ? __ldg(&dst[e])
                            : __ldg(&inter[(size_t)e * NUMK + slot - 1]);
    float sx = __ldg(&loc[si * 3]),    sy = __ldg(&loc[si * 3 + 1]),    sz = __ldg(&loc[si * 3 + 2]);
    float bx = __ldg(&loc[other * 3]), by = __ldg(&loc[other * 3 + 1]), bz = __ldg(&loc[other * 3 + 2]);
    float dx = sx - bx, dy = sy - by, dz = sz - bz;
    float d2 = dx * dx + dy * dy + dz * dz;     // squared-vs-squared compare
    int pos = 0;
#pragma unroll
    for (int step = 32; step >= 1; step >>= 1)
        if (pos + step <= NBND && sb2[pos + step - 1] < d2) pos += step;
    g_pk[slot][e] = (other << 6) | pos;
}

// One warp per edge: gathers + FMA + red.v4. No shuffles, no search.
__global__ __launch_bounds__(256) void k_feat(
    const float* __restrict__ feat,
    const int* __restrict__ src, const int* __restrict__ dst)
{
    int t = threadIdx.x;
    int lane = t & 31;
    int e = blockIdx.x * 8 + (t >> 5);
    if (e >= N_EDGES) return;

    int si = __ldg(&src[e]);
    int di = __ldg(&dst[e]);
    float sc = rsqrtf(fmaxf(__ldg(&g_c0[di]), 1.f)) *
               rsqrtf(fmaxf(__ldg(&g_c2[si]), 1.f));
    float* yrow = g_y + (size_t)di * 128;

    if (lane < 16) {
        int j = lane * 4;
        int b1 = __ldg(&g_pk[0][e]) & 63;    // same-address broadcast
        float4 h  = *reinterpret_cast<const float4*>(feat + (size_t)si * FDIM + j);
        float4 tt = *reinterpret_cast<const float4*>(g_T + b1 * FDIM + j);
        red_add4(yrow + j, sc * h.x * tt.x, sc * h.y * tt.y,
                           sc * h.z * tt.z, sc * h.w * tt.w);
        if (lane == 0) atomicAdd(&g_s[di], sc);
    } else {
        int j = (lane - 16) * 4;
        float ax = 0.f, ay = 0.f, az = 0.f, aw = 0.f;
#pragma unroll
        for (int k = 0; k < NUMK; k++) {
            int pv = __ldg(&g_pk[k + 1][e]);  // same-address broadcast
            int id = pv >> 6, bk = pv & 63;
            float4 h  = *reinterpret_cast<const float4*>(feat + (size_t)id * FDIM + j);
            float4 tt = *reinterpret_cast<const float4*>(g_T + bk * FDIM + j);
            ax += h.x * tt.x; ay += h.y * tt.y;
            az += h.z * tt.z; aw += h.w * tt.w;
        }
        float f4 = sc * 0.25f;
        red_add4(yrow + 64 + j, f4 * ax, f4 * ay, f4 * az, f4 * aw);
    }
}

// out[v][f] = sum_j y[v][j] * W[f][j] + s[v] * b[f]
__global__ __launch_bounds__(256) void k_gemm(
    const float* __restrict__ W, const float* __restrict__ bvec,
    float* __restrict__ out)
{
    extern __shared__ float smem[];
    float* sW = smem;
    float* sY = smem + 128 * GP;
    int t = threadIdx.x;
    int vbase = blockIdx.x * 64;

    for (int idx = t; idx < FDIM * 128; idx += 256) {
        int f = idx >> 7, j = idx & 127;
        sW[j * GP + f] = W[idx];
    }
    for (int idx = t; idx < 64 * 128; idx += 256) {
        int v = idx >> 7, j = idx & 127;
        int gv = vbase + v;
        sY[j * GP + v] = (gv < N_NODES) ? g_y[(size_t)gv * 128 + j] : 0.f;
    }
    __syncthreads();

    int f0 = (t & 15) * 4;
    int v0 = (t >> 4) * 4;
    float acc[4][4];
#pragma unroll
    for (int a = 0; a < 4; a++)
#pragma unroll
        for (int b = 0; b < 4; b++) acc[a][b] = 0.f;

#pragma unroll 4
    for (int j = 0; j < 128; j++) {
        float4 wv = *reinterpret_cast<float4*>(&sW[j * GP + f0]);
        float4 yv = *reinterpret_cast<float4*>(&sY[j * GP + v0]);
        float wr[4] = {wv.x, wv.y, wv.z, wv.w};
        float yr[4] = {yv.x, yv.y, yv.z, yv.w};
#pragma unroll
        for (int a = 0; a < 4; a++)
#pragma unroll
            for (int b = 0; b < 4; b++) acc[a][b] += yr[a] * wr[b];
    }

    float4 bb = *reinterpret_cast<const float4*>(bvec + f0);
#pragma unroll
    for (int a = 0; a < 4; a++) {
        int v = vbase + v0 + a;
        if (v < N_NODES) {
            float sv = g_s[v];
            float4 o;
            o.x = acc[a][0] + sv * bb.x;
            o.y = acc[a][1] + sv * bb.y;
            o.z = acc[a][2] + sv * bb.z;
            o.w = acc[a][3] + sv * bb.w;
            *reinterpret_cast<float4*>(out + (size_t)v * FDIM + f0) = o;
        }
    }
}

extern "C" void kernel_launch(void* const* d_in, const int* in_sizes, int n_in,
                              void* d_out, int out_size) {
    const float* feat = (const float*)d_in[0];
    const float* loc  = (const float*)d_in[1];
    const float* bnd  = (const float*)d_in[2];
    const float* emb  = (const float*)d_in[3];
    const float* gw   = (const float*)d_in[4];
    const float* aggw = (const float*)d_in[5];
    const float* aggb = (const float*)d_in[6];
    const int* src   = (const int*)d_in[7];
    const int* dst   = (const int*)d_in[8];
    const int* inter = (const int*)d_in[9];
    float* out = (float*)d_out;

    k_prep<<<1024, 256>>>(emb, gw);                                   // 1
    k_deg<<<(N_EDGES + 255) / 256, 256>>>(src, dst);                  // 2
    k_dist<<<(N_EDGES + 63) / 64, 320>>>(loc, bnd, src, dst, inter);  // 3
    k_feat<<<(N_EDGES + 7) / 8, 256>>>(feat, src, dst);               // 4 (profiled)
    size_t smem = 2 * 128 * GP * sizeof(float);
    cudaFuncSetAttribute(k_gemm, cudaFuncAttributeMaxDynamicSharedMemorySize, (int)smem);
    k_gemm<<<(N_NODES + 63) / 64, 256, smem>>>(aggw, aggb, out);      // 5
}